// round 7
// baseline (speedup 1.0000x reference)
#include <cuda_runtime.h>
#include <math.h>
#include <stdint.h>

#define TBITS 19
#define TSIZE (1u << TBITS)
#define TMASK (TSIZE - 1u)
#define NLEV 16
#define BLOCKA 256
#define BLOCKB 128
#define CH 32768   // chunk size: scratch = 64*CH float2 = 16.8MB, L2-resident

// scratch: per (level l, slot k) a float2 plane of CH points
//   k=0: (F[2l], F[2l+1]) ; k=1: (Gx0,Gx1) ; k=2: (Gy0,Gy1) ; k=3: (Gz0,Gz1)
__device__ float2 g_scratch[64 * CH];

__device__ __forceinline__ float shY(int c, float x, float y, float z,
                                     float xx, float yy, float zz,
                                     float xy, float yz, float xz)
{
    switch (c) {
    case 0:  return 0.28209479177387814f;
    case 1:  return -0.4886025119029199f * y;
    case 2:  return  0.4886025119029199f * z;
    case 3:  return -0.4886025119029199f * x;
    case 4:  return  1.0925484305920792f * xy;
    case 5:  return -1.0925484305920792f * yz;
    case 6:  return  0.31539156525252005f * (2.f * zz - xx - yy);
    case 7:  return -1.0925484305920792f * xz;
    case 8:  return  0.5462742152960396f * (xx - yy);
    case 9:  return -0.5900435899266435f * y * (3.f * xx - yy);
    case 10: return  2.890611442640554f  * xy * z;
    case 11: return -0.4570457994644658f * y * (4.f * zz - xx - yy);
    case 12: return  0.3731763325901154f * z * (2.f * zz - 3.f * xx - 3.f * yy);
    case 13: return -0.4570457994644658f * x * (4.f * zz - xx - yy);
    case 14: return  1.445305721320277f  * z * (xx - yy);
    case 15: return -0.5900435899266435f * x * (xx - 3.f * yy);
    }
    return 0.f;
}

// ---------------- Kernel A: hash-grid gather, one (point, level) per thread ----
__global__ __launch_bounds__(BLOCKA)
void ngp_encode_kernel(const float* __restrict__ pos,
                       const float* __restrict__ table,
                       const float* __restrict__ aabb,
                       int baseN, int chunk)
{
    __shared__ float sres;
    const int l = blockIdx.y;
    if (threadIdx.x == 0) {
        // Replicate reference: s = exp((ln(4096)-ln(16))/15); res_l = f32(16 * s^l)
        double s = exp(0.36967849629863747);
        sres = (float)(16.0 * pow(s, (double)l));
    }
    __syncthreads();

    const int n = blockIdx.x * BLOCKA + threadIdx.x;
    if (n >= chunk) return;
    const int ng = baseN + n;

    float P0 = pos[3 * ng + 0], P1 = pos[3 * ng + 1], P2 = pos[3 * ng + 2];
    float a0 = aabb[0], a1 = aabb[1], a2 = aabb[2];
    float s0 = fmaxf(aabb[3] - a0, 1e-6f);
    float s1 = fmaxf(aabb[4] - a1, 1e-6f);
    float s2 = fmaxf(aabb[5] - a2, 1e-6f);
    float q0 = __fdiv_rn(P0 - a0, s0);
    float q1 = __fdiv_rn(P1 - a1, s1);
    float q2 = __fdiv_rn(P2 - a2, s2);
    float pn0 = fminf(fmaxf(q0, 0.f), 1.f);
    float pn1 = fminf(fmaxf(q1, 0.f), 1.f);
    float pn2 = fminf(fmaxf(q2, 0.f), 1.f);

    const float res = sres;
    float px = pn0 * res, py = pn1 * res, pz = pn2 * res;
    float fx = floorf(px), fy = floorf(py), fz = floorf(pz);
    float wx = px - fx, wy = py - fy, wz = pz - fz;
    unsigned ux = (unsigned)fx, uy = (unsigned)fy, uz = (unsigned)fz;
    unsigned hx0 = ux,                hx1 = ux + 1u;
    unsigned hy0 = uy * 2654435761u,  hy1 = (uy + 1u) * 2654435761u;
    unsigned hz0 = uz * 805459861u,   hz1 = (uz + 1u) * 805459861u;
    const float2* tab = ((const float2*)table) + (size_t)l * TSIZE;

    // batch all 8 gathers first (max MLP), then accumulate in the SAME order
    float2 fv[8];
    #pragma unroll
    for (int c = 0; c < 8; c++) {
        const int bx = (c >> 2) & 1, by = (c >> 1) & 1, bz = c & 1;
        unsigned hh = (bx ? hx1 : hx0) ^ (by ? hy1 : hy0) ^ (bz ? hz1 : hz0);
        fv[c] = __ldg(&tab[hh & TMASK]);
    }

    float f0a = 0.f, f0b = 0.f, f1a = 0.f, f1b = 0.f;
    float gx0a = 0.f, gx0b = 0.f, gx1a = 0.f, gx1b = 0.f;
    float gy0a = 0.f, gy0b = 0.f, gy1a = 0.f, gy1b = 0.f;
    float gz0a = 0.f, gz0b = 0.f, gz1a = 0.f, gz1b = 0.f;

    #pragma unroll
    for (int c = 0; c < 8; c++) {
        const int bx = (c >> 2) & 1, by = (c >> 1) & 1, bz = c & 1;
        float2 f = fv[c];
        float tx = bx ? wx : (1.f - wx);
        float ty = by ? wy : (1.f - wy);
        float tz = bz ? wz : (1.f - wz);
        float pyz = ty * tz;
        float pxz = tx * tz;
        float pxy = tx * ty;
        float wc  = tx * pyz;
        float sx = bx ? pyz : -pyz;
        float sy = by ? pxz : -pxz;
        float sz = bz ? pxy : -pxy;
        if (c & 1) {
            f0b = fmaf(f.x, wc, f0b);   f1b = fmaf(f.y, wc, f1b);
            gx0b = fmaf(f.x, sx, gx0b); gx1b = fmaf(f.y, sx, gx1b);
            gy0b = fmaf(f.x, sy, gy0b); gy1b = fmaf(f.y, sy, gy1b);
            gz0b = fmaf(f.x, sz, gz0b); gz1b = fmaf(f.y, sz, gz1b);
        } else {
            f0a = fmaf(f.x, wc, f0a);   f1a = fmaf(f.y, wc, f1a);
            gx0a = fmaf(f.x, sx, gx0a); gx1a = fmaf(f.y, sx, gx1a);
            gy0a = fmaf(f.x, sy, gy0a); gy1a = fmaf(f.y, sy, gy1a);
            gz0a = fmaf(f.x, sz, gz0a); gz1a = fmaf(f.y, sz, gz1a);
        }
    }

    float2* S = g_scratch;
    S[(l * 4 + 0) * CH + n] = make_float2(f0a + f0b, f1a + f1b);
    S[(l * 4 + 1) * CH + n] = make_float2((gx0a + gx0b) * res, (gx1a + gx1b) * res);
    S[(l * 4 + 2) * CH + n] = make_float2((gy0a + gy0b) * res, (gy1a + gy1b) * res);
    S[(l * 4 + 3) * CH + n] = make_float2((gz0a + gz0b) * res, (gz1a + gz1b) * res);
}

// ---------------- Kernel B: MLP fwd + bwd + SH, streaming F/G from scratch ----
__global__ __launch_bounds__(BLOCKB, 5)
void ngp_mlp_kernel(const float* __restrict__ pos,
                    const float* __restrict__ rx,
                    const float* __restrict__ W1,
                    const float* __restrict__ W2,
                    const float* __restrict__ aabb,
                    const int*   __restrict__ degp,
                    float* __restrict__ out,
                    int baseN, int chunk, int N)
{
    __shared__ float sW1[1024];
    __shared__ float sW2[1024];
    __shared__ __align__(16) float sOut[BLOCKB * 39];

    const int tid = threadIdx.x;
    for (int i = tid; i < 1024; i += BLOCKB) {
        sW1[i] = W1[i];
        sW2[i] = W2[i];
    }
    __syncthreads();

    const int n = blockIdx.x * BLOCKB + tid;
    const int ng = baseN + n;
    const double C0d = 0.28209479177387814;
    const float2* S = g_scratch;

    if (n < chunk) {
        float P0 = pos[3 * ng + 0], P1 = pos[3 * ng + 1], P2 = pos[3 * ng + 2];
        float a0 = aabb[0], a1 = aabb[1], a2 = aabb[2];
        float s0 = fmaxf(aabb[3] - a0, 1e-6f);
        float s1 = fmaxf(aabb[4] - a1, 1e-6f);
        float s2 = fmaxf(aabb[5] - a2, 1e-6f);
        float q0 = __fdiv_rn(P0 - a0, s0);
        float q1 = __fdiv_rn(P1 - a1, s1);
        float q2 = __fdiv_rn(P2 - a2, s2);
        bool sel = (q0 >= 0.f) && (q0 <= 1.f) &&
                   (q1 >= 0.f) && (q1 <= 1.f) &&
                   (q2 >= 0.f) && (q2 <= 1.f);

        // ---- load F from scratch (coalesced float2) ----
        float F[32];
        #pragma unroll
        for (int l = 0; l < NLEV; l++) {
            float2 fl = S[(l * 4 + 0) * CH + n];
            F[2 * l] = fl.x; F[2 * l + 1] = fl.y;
        }

        // ---- MLP layer 1: h = relu(F @ W1), 4-way split (F dies here) ----
        float h[32];
        #pragma unroll
        for (int j = 0; j < 32; j++) {
            float a0_ = 0.f, a1_ = 0.f, a2_ = 0.f, a3_ = 0.f;
            #pragma unroll
            for (int i = 0; i < 32; i += 4) {
                a0_ = fmaf(F[i],     sW1[(i)     * 32 + j], a0_);
                a1_ = fmaf(F[i + 1], sW1[(i + 1) * 32 + j], a1_);
                a2_ = fmaf(F[i + 2], sW1[(i + 2) * 32 + j], a2_);
                a3_ = fmaf(F[i + 3], sW1[(i + 3) * 32 + j], a3_);
            }
            h[j] = fmaxf((a0_ + a2_) + (a1_ + a3_), 0.f);
        }

        // ---- view direction + SH, layer 2 early (before backward) ----
        int deg = 3;
        if (degp) {
            int v = degp[0];
            if (v >= 0 && v <= 8) deg = v;
        }
        int nact = (deg + 1) * (deg + 1);
        float dx = rx[0] - P0, dy = rx[1] - P1, dz = rx[2] - P2;
        float dn = __fsqrt_rn(dx * dx + dy * dy + dz * dz);
        float dnc = fmaxf(dn, 1e-20f);
        float X = __fdiv_rn(dx, dnc), Y = __fdiv_rn(dy, dnc), Z = __fdiv_rn(dz, dnc);
        float xx = X * X, yy = Y * Y, zz = Z * Z;
        float xy = X * Y, yz = Y * Z, xz = X * Z;

        float* row = &sOut[tid * 39];
        float scat0 = 0.f, scat1 = 0.f;
        #pragma unroll
        for (int c = 0; c < 16; c++) {
            float v0a = 0.f, v0b = 0.f, v1a = 0.f, v1b = 0.f;
            #pragma unroll
            for (int j = 0; j < 32; j += 2) {
                v0a = fmaf(h[j],     sW2[(j)     * 32 + 2 * c],     v0a);
                v1a = fmaf(h[j],     sW2[(j)     * 32 + 2 * c + 1], v1a);
                v0b = fmaf(h[j + 1], sW2[(j + 1) * 32 + 2 * c],     v0b);
                v1b = fmaf(h[j + 1], sW2[(j + 1) * 32 + 2 * c + 1], v1b);
            }
            float v0 = v0a + v0b, v1 = v1a + v1b;
            float Yc = shY(c, X, Y, Z, xx, yy, zz, xy, yz, xz);
            if (c < nact) {
                scat0 = fmaf(Yc, v0, scat0);
                scat1 = fmaf(Yc, v1, scat1);
            }
            row[7 + 2 * c]     = sel ? v0 : 0.f;
            row[7 + 2 * c + 1] = sel ? v1 : 0.f;
        }
        row[2] = sel ? scat0 : 0.f;
        row[3] = sel ? scat1 : 0.f;

        // ---- dens in fp64 ----
        double dd0 = 0.0, dd1 = 0.0;
        #pragma unroll
        for (int j = 0; j < 32; j++) {
            double hj = (double)h[j];
            dd0 = fma(hj, (double)sW2[j * 32 + 0], dd0);
            dd1 = fma(hj, (double)sW2[j * 32 + 1], dd1);
        }
        dd0 *= C0d; dd1 *= C0d;
        row[0] = sel ? (float)dd0 : 0.f;
        row[1] = sel ? (float)dd1 : 0.f;

        // ---- backward (fp64 cotangent); h dies at gj ----
        double rr = sqrt(dd0 * dd0 + dd1 * dd1);
        double u0 = 0.0, u1 = 0.0;
        if (rr > 0.0) { u0 = dd0 / rr; u1 = dd1 / rr; }
        double cu0 = C0d * u0, cu1 = C0d * u1;

        float gj[32];
        #pragma unroll
        for (int j = 0; j < 32; j++) {
            double v = fma(cu0, (double)sW2[j * 32 + 0], cu1 * (double)sW2[j * 32 + 1]);
            gj[j] = (h[j] > 0.f) ? (float)v : 0.f;
        }

        float df[32];
        #pragma unroll
        for (int i = 0; i < 32; i++) {
            float a0_ = 0.f, a1_ = 0.f, a2_ = 0.f, a3_ = 0.f;
            #pragma unroll
            for (int j = 0; j < 32; j += 4) {
                a0_ = fmaf(gj[j],     sW1[i * 32 + j],     a0_);
                a1_ = fmaf(gj[j + 1], sW1[i * 32 + j + 1], a1_);
                a2_ = fmaf(gj[j + 2], sW1[i * 32 + j + 2], a2_);
                a3_ = fmaf(gj[j + 3], sW1[i * 32 + j + 3], a3_);
            }
            df[i] = (a0_ + a2_) + (a1_ + a3_);
        }

        // ---- final gradient reduction in fp64, streaming G from scratch ----
        double gpx = 0.0, gpy = 0.0, gpz = 0.0;
        #pragma unroll
        for (int l = 0; l < NLEV; l++) {
            double d0 = (double)df[2 * l], d1 = (double)df[2 * l + 1];
            float2 gx = S[(l * 4 + 1) * CH + n];
            float2 gy = S[(l * 4 + 2) * CH + n];
            float2 gz = S[(l * 4 + 3) * CH + n];
            gpx = fma(d0, (double)gx.x, fma(d1, (double)gx.y, gpx));
            gpy = fma(d0, (double)gy.x, fma(d1, (double)gy.y, gpy));
            gpz = fma(d0, (double)gz.x, fma(d1, (double)gz.y, gpz));
        }
        double gw0 = gpx / (double)s0;
        double gw1 = gpy / (double)s1;
        double gw2 = gpz / (double)s2;
        double gn = sqrt(gw0 * gw0 + gw1 * gw1 + gw2 * gw2);
        double gd = fmax(gn, 1e-20);
        row[4] = sel ? (float)(-gw0 / gd) : 0.f;
        row[5] = sel ? (float)(-gw1 / gd) : 0.f;
        row[6] = sel ? (float)(-gw2 / gd) : 0.f;
    }

    __syncthreads();

    // ---- coalesced staged output ----
    int base = baseN + blockIdx.x * BLOCKB;
    int npts = N - base;
    if (npts >= BLOCKB) {
        const float4* s4 = (const float4*)sOut;
        float4* o4 = (float4*)(out + (size_t)base * 39);
        #pragma unroll 4
        for (int i = tid; i < (BLOCKB * 39) / 4; i += BLOCKB)
            o4[i] = s4[i];
    } else if (npts > 0) {
        for (int i = tid; i < npts * 39; i += BLOCKB)
            out[(size_t)base * 39 + i] = sOut[i];
    }
}

extern "C" void kernel_launch(void* const* d_in, const int* in_sizes, int n_in,
                              void* d_out, int out_size)
{
    const float* pos   = (const float*)d_in[0];
    const float* rx    = (const float*)d_in[1];
    const float* table = (const float*)d_in[2];
    const float* W1    = (const float*)d_in[3];
    const float* W2    = (const float*)d_in[4];
    const float* aabb  = (const float*)d_in[5];
    const int*   degp  = (n_in > 6) ? (const int*)d_in[6] : nullptr;

    int N = in_sizes[0] / 3;

    for (int base = 0; base < N; base += CH) {
        int chunk = (N - base < CH) ? (N - base) : CH;
        dim3 gridA((chunk + BLOCKA - 1) / BLOCKA, NLEV);
        ngp_encode_kernel<<<gridA, BLOCKA>>>(pos, table, aabb, base, chunk);
        int gridB = (chunk + BLOCKB - 1) / BLOCKB;
        ngp_mlp_kernel<<<gridB, BLOCKB>>>(pos, rx, W1, W2, aabb, degp,
                                          (float*)d_out, base, chunk, N);
    }
}

// round 8
// speedup vs baseline: 1.2438x; 1.2438x over previous
#include <cuda_runtime.h>
#include <math.h>
#include <stdint.h>

#define TBITS 19
#define TSIZE (1u << TBITS)
#define TMASK (TSIZE - 1u)
#define NLEV 16
#define BLOCKA 256
#define BLOCKB 128
#define CH 131072  // 2 chunks: B grid=1024 blocks (full 5-block/SM residency), scratch 67MB

// scratch: per (level l, slot k) a float2 plane of CH points
//   k=0: (F[2l], F[2l+1]) ; k=1: (Gx0,Gx1) ; k=2: (Gy0,Gy1) ; k=3: (Gz0,Gz1)
__device__ float2 g_scratch[64 * CH];

__device__ __forceinline__ float shY(int c, float x, float y, float z,
                                     float xx, float yy, float zz,
                                     float xy, float yz, float xz)
{
    switch (c) {
    case 0:  return 0.28209479177387814f;
    case 1:  return -0.4886025119029199f * y;
    case 2:  return  0.4886025119029199f * z;
    case 3:  return -0.4886025119029199f * x;
    case 4:  return  1.0925484305920792f * xy;
    case 5:  return -1.0925484305920792f * yz;
    case 6:  return  0.31539156525252005f * (2.f * zz - xx - yy);
    case 7:  return -1.0925484305920792f * xz;
    case 8:  return  0.5462742152960396f * (xx - yy);
    case 9:  return -0.5900435899266435f * y * (3.f * xx - yy);
    case 10: return  2.890611442640554f  * xy * z;
    case 11: return -0.4570457994644658f * y * (4.f * zz - xx - yy);
    case 12: return  0.3731763325901154f * z * (2.f * zz - 3.f * xx - 3.f * yy);
    case 13: return -0.4570457994644658f * x * (4.f * zz - xx - yy);
    case 14: return  1.445305721320277f  * z * (xx - yy);
    case 15: return -0.5900435899266435f * x * (xx - 3.f * yy);
    }
    return 0.f;
}

// ---------------- Kernel A: hash-grid gather, one (point, level) per thread ----
__global__ __launch_bounds__(BLOCKA)
void ngp_encode_kernel(const float* __restrict__ pos,
                       const float* __restrict__ table,
                       const float* __restrict__ aabb,
                       int baseN, int chunk)
{
    __shared__ float sres;
    const int l = blockIdx.y;
    if (threadIdx.x == 0) {
        // Replicate reference: s = exp((ln(4096)-ln(16))/15); res_l = f32(16 * s^l)
        double s = exp(0.36967849629863747);
        sres = (float)(16.0 * pow(s, (double)l));
    }
    __syncthreads();

    const int n = blockIdx.x * BLOCKA + threadIdx.x;
    if (n >= chunk) return;
    const int ng = baseN + n;

    float P0 = pos[3 * ng + 0], P1 = pos[3 * ng + 1], P2 = pos[3 * ng + 2];
    float a0 = aabb[0], a1 = aabb[1], a2 = aabb[2];
    float s0 = fmaxf(aabb[3] - a0, 1e-6f);
    float s1 = fmaxf(aabb[4] - a1, 1e-6f);
    float s2 = fmaxf(aabb[5] - a2, 1e-6f);
    float q0 = __fdiv_rn(P0 - a0, s0);
    float q1 = __fdiv_rn(P1 - a1, s1);
    float q2 = __fdiv_rn(P2 - a2, s2);
    float pn0 = fminf(fmaxf(q0, 0.f), 1.f);
    float pn1 = fminf(fmaxf(q1, 0.f), 1.f);
    float pn2 = fminf(fmaxf(q2, 0.f), 1.f);

    const float res = sres;
    float px = pn0 * res, py = pn1 * res, pz = pn2 * res;
    float fx = floorf(px), fy = floorf(py), fz = floorf(pz);
    float wx = px - fx, wy = py - fy, wz = pz - fz;
    unsigned ux = (unsigned)fx, uy = (unsigned)fy, uz = (unsigned)fz;
    unsigned hx0 = ux,                hx1 = ux + 1u;
    unsigned hy0 = uy * 2654435761u,  hy1 = (uy + 1u) * 2654435761u;
    unsigned hz0 = uz * 805459861u,   hz1 = (uz + 1u) * 805459861u;
    const float2* tab = ((const float2*)table) + (size_t)l * TSIZE;

    // batch all 8 gathers first (max MLP), then accumulate in the SAME order
    float2 fv[8];
    #pragma unroll
    for (int c = 0; c < 8; c++) {
        const int bx = (c >> 2) & 1, by = (c >> 1) & 1, bz = c & 1;
        unsigned hh = (bx ? hx1 : hx0) ^ (by ? hy1 : hy0) ^ (bz ? hz1 : hz0);
        fv[c] = __ldg(&tab[hh & TMASK]);
    }

    float f0a = 0.f, f0b = 0.f, f1a = 0.f, f1b = 0.f;
    float gx0a = 0.f, gx0b = 0.f, gx1a = 0.f, gx1b = 0.f;
    float gy0a = 0.f, gy0b = 0.f, gy1a = 0.f, gy1b = 0.f;
    float gz0a = 0.f, gz0b = 0.f, gz1a = 0.f, gz1b = 0.f;

    #pragma unroll
    for (int c = 0; c < 8; c++) {
        const int bx = (c >> 2) & 1, by = (c >> 1) & 1, bz = c & 1;
        float2 f = fv[c];
        float tx = bx ? wx : (1.f - wx);
        float ty = by ? wy : (1.f - wy);
        float tz = bz ? wz : (1.f - wz);
        float pyz = ty * tz;
        float pxz = tx * tz;
        float pxy = tx * ty;
        float wc  = tx * pyz;
        float sx = bx ? pyz : -pyz;
        float sy = by ? pxz : -pxz;
        float sz = bz ? pxy : -pxy;
        if (c & 1) {
            f0b = fmaf(f.x, wc, f0b);   f1b = fmaf(f.y, wc, f1b);
            gx0b = fmaf(f.x, sx, gx0b); gx1b = fmaf(f.y, sx, gx1b);
            gy0b = fmaf(f.x, sy, gy0b); gy1b = fmaf(f.y, sy, gy1b);
            gz0b = fmaf(f.x, sz, gz0b); gz1b = fmaf(f.y, sz, gz1b);
        } else {
            f0a = fmaf(f.x, wc, f0a);   f1a = fmaf(f.y, wc, f1a);
            gx0a = fmaf(f.x, sx, gx0a); gx1a = fmaf(f.y, sx, gx1a);
            gy0a = fmaf(f.x, sy, gy0a); gy1a = fmaf(f.y, sy, gy1a);
            gz0a = fmaf(f.x, sz, gz0a); gz1a = fmaf(f.y, sz, gz1a);
        }
    }

    float2* S = g_scratch;
    S[(size_t)(l * 4 + 0) * CH + n] = make_float2(f0a + f0b, f1a + f1b);
    S[(size_t)(l * 4 + 1) * CH + n] = make_float2((gx0a + gx0b) * res, (gx1a + gx1b) * res);
    S[(size_t)(l * 4 + 2) * CH + n] = make_float2((gy0a + gy0b) * res, (gy1a + gy1b) * res);
    S[(size_t)(l * 4 + 3) * CH + n] = make_float2((gz0a + gz0b) * res, (gz1a + gz1b) * res);
}

// ---------------- Kernel B: MLP fwd + bwd + SH, streaming F/G from scratch ----
__global__ __launch_bounds__(BLOCKB, 5)
void ngp_mlp_kernel(const float* __restrict__ pos,
                    const float* __restrict__ rx,
                    const float* __restrict__ W1,
                    const float* __restrict__ W2,
                    const float* __restrict__ aabb,
                    const int*   __restrict__ degp,
                    float* __restrict__ out,
                    int baseN, int chunk, int N)
{
    __shared__ float sW1[1024];
    __shared__ float sW2[1024];
    __shared__ __align__(16) float sOut[BLOCKB * 39];

    const int tid = threadIdx.x;
    for (int i = tid; i < 1024; i += BLOCKB) {
        sW1[i] = W1[i];
        sW2[i] = W2[i];
    }
    __syncthreads();

    const int n = blockIdx.x * BLOCKB + tid;
    const int ng = baseN + n;
    const double C0d = 0.28209479177387814;
    const float2* S = g_scratch;

    if (n < chunk) {
        float P0 = pos[3 * ng + 0], P1 = pos[3 * ng + 1], P2 = pos[3 * ng + 2];
        float a0 = aabb[0], a1 = aabb[1], a2 = aabb[2];
        float s0 = fmaxf(aabb[3] - a0, 1e-6f);
        float s1 = fmaxf(aabb[4] - a1, 1e-6f);
        float s2 = fmaxf(aabb[5] - a2, 1e-6f);
        float q0 = __fdiv_rn(P0 - a0, s0);
        float q1 = __fdiv_rn(P1 - a1, s1);
        float q2 = __fdiv_rn(P2 - a2, s2);
        bool sel = (q0 >= 0.f) && (q0 <= 1.f) &&
                   (q1 >= 0.f) && (q1 <= 1.f) &&
                   (q2 >= 0.f) && (q2 <= 1.f);

        // ---- load F from scratch (coalesced float2) ----
        float F[32];
        #pragma unroll
        for (int l = 0; l < NLEV; l++) {
            float2 fl = __ldg(&S[(size_t)(l * 4 + 0) * CH + n]);
            F[2 * l] = fl.x; F[2 * l + 1] = fl.y;
        }

        // ---- MLP layer 1: h = relu(F @ W1), 4-way split (F dies here) ----
        float h[32];
        #pragma unroll
        for (int j = 0; j < 32; j++) {
            float a0_ = 0.f, a1_ = 0.f, a2_ = 0.f, a3_ = 0.f;
            #pragma unroll
            for (int i = 0; i < 32; i += 4) {
                a0_ = fmaf(F[i],     sW1[(i)     * 32 + j], a0_);
                a1_ = fmaf(F[i + 1], sW1[(i + 1) * 32 + j], a1_);
                a2_ = fmaf(F[i + 2], sW1[(i + 2) * 32 + j], a2_);
                a3_ = fmaf(F[i + 3], sW1[(i + 3) * 32 + j], a3_);
            }
            h[j] = fmaxf((a0_ + a2_) + (a1_ + a3_), 0.f);
        }

        // ---- view direction + SH, layer 2 early (before backward) ----
        int deg = 3;
        if (degp) {
            int v = degp[0];
            if (v >= 0 && v <= 8) deg = v;
        }
        int nact = (deg + 1) * (deg + 1);
        float dx = rx[0] - P0, dy = rx[1] - P1, dz = rx[2] - P2;
        float dn = __fsqrt_rn(dx * dx + dy * dy + dz * dz);
        float dnc = fmaxf(dn, 1e-20f);
        float X = __fdiv_rn(dx, dnc), Y = __fdiv_rn(dy, dnc), Z = __fdiv_rn(dz, dnc);
        float xx = X * X, yy = Y * Y, zz = Z * Z;
        float xy = X * Y, yz = Y * Z, xz = X * Z;

        float* row = &sOut[tid * 39];
        float scat0 = 0.f, scat1 = 0.f;
        #pragma unroll
        for (int c = 0; c < 16; c++) {
            float v0a = 0.f, v0b = 0.f, v1a = 0.f, v1b = 0.f;
            #pragma unroll
            for (int j = 0; j < 32; j += 2) {
                v0a = fmaf(h[j],     sW2[(j)     * 32 + 2 * c],     v0a);
                v1a = fmaf(h[j],     sW2[(j)     * 32 + 2 * c + 1], v1a);
                v0b = fmaf(h[j + 1], sW2[(j + 1) * 32 + 2 * c],     v0b);
                v1b = fmaf(h[j + 1], sW2[(j + 1) * 32 + 2 * c + 1], v1b);
            }
            float v0 = v0a + v0b, v1 = v1a + v1b;
            float Yc = shY(c, X, Y, Z, xx, yy, zz, xy, yz, xz);
            if (c < nact) {
                scat0 = fmaf(Yc, v0, scat0);
                scat1 = fmaf(Yc, v1, scat1);
            }
            row[7 + 2 * c]     = sel ? v0 : 0.f;
            row[7 + 2 * c + 1] = sel ? v1 : 0.f;
        }
        row[2] = sel ? scat0 : 0.f;
        row[3] = sel ? scat1 : 0.f;

        // ---- dens in fp64 ----
        double dd0 = 0.0, dd1 = 0.0;
        #pragma unroll
        for (int j = 0; j < 32; j++) {
            double hj = (double)h[j];
            dd0 = fma(hj, (double)sW2[j * 32 + 0], dd0);
            dd1 = fma(hj, (double)sW2[j * 32 + 1], dd1);
        }
        dd0 *= C0d; dd1 *= C0d;
        row[0] = sel ? (float)dd0 : 0.f;
        row[1] = sel ? (float)dd1 : 0.f;

        // ---- backward (fp64 cotangent); h dies at gj ----
        double rr = sqrt(dd0 * dd0 + dd1 * dd1);
        double u0 = 0.0, u1 = 0.0;
        if (rr > 0.0) { u0 = dd0 / rr; u1 = dd1 / rr; }
        double cu0 = C0d * u0, cu1 = C0d * u1;

        float gj[32];
        #pragma unroll
        for (int j = 0; j < 32; j++) {
            double v = fma(cu0, (double)sW2[j * 32 + 0], cu1 * (double)sW2[j * 32 + 1]);
            gj[j] = (h[j] > 0.f) ? (float)v : 0.f;
        }

        float df[32];
        #pragma unroll
        for (int i = 0; i < 32; i++) {
            float a0_ = 0.f, a1_ = 0.f, a2_ = 0.f, a3_ = 0.f;
            #pragma unroll
            for (int j = 0; j < 32; j += 4) {
                a0_ = fmaf(gj[j],     sW1[i * 32 + j],     a0_);
                a1_ = fmaf(gj[j + 1], sW1[i * 32 + j + 1], a1_);
                a2_ = fmaf(gj[j + 2], sW1[i * 32 + j + 2], a2_);
                a3_ = fmaf(gj[j + 3], sW1[i * 32 + j + 3], a3_);
            }
            df[i] = (a0_ + a2_) + (a1_ + a3_);
        }

        // ---- final gradient reduction in fp64, streaming G from scratch ----
        double gpx = 0.0, gpy = 0.0, gpz = 0.0;
        #pragma unroll
        for (int l = 0; l < NLEV; l++) {
            double d0 = (double)df[2 * l], d1 = (double)df[2 * l + 1];
            float2 gx = __ldg(&S[(size_t)(l * 4 + 1) * CH + n]);
            float2 gy = __ldg(&S[(size_t)(l * 4 + 2) * CH + n]);
            float2 gz = __ldg(&S[(size_t)(l * 4 + 3) * CH + n]);
            gpx = fma(d0, (double)gx.x, fma(d1, (double)gx.y, gpx));
            gpy = fma(d0, (double)gy.x, fma(d1, (double)gy.y, gpy));
            gpz = fma(d0, (double)gz.x, fma(d1, (double)gz.y, gpz));
        }
        double gw0 = gpx / (double)s0;
        double gw1 = gpy / (double)s1;
        double gw2 = gpz / (double)s2;
        double gn = sqrt(gw0 * gw0 + gw1 * gw1 + gw2 * gw2);
        double gd = fmax(gn, 1e-20);
        row[4] = sel ? (float)(-gw0 / gd) : 0.f;
        row[5] = sel ? (float)(-gw1 / gd) : 0.f;
        row[6] = sel ? (float)(-gw2 / gd) : 0.f;
    }

    __syncthreads();

    // ---- coalesced staged output ----
    int base = baseN + blockIdx.x * BLOCKB;
    int npts = N - base;
    if (npts >= BLOCKB) {
        const float4* s4 = (const float4*)sOut;
        float4* o4 = (float4*)(out + (size_t)base * 39);
        #pragma unroll 4
        for (int i = tid; i < (BLOCKB * 39) / 4; i += BLOCKB)
            o4[i] = s4[i];
    } else if (npts > 0) {
        for (int i = tid; i < npts * 39; i += BLOCKB)
            out[(size_t)base * 39 + i] = sOut[i];
    }
}

extern "C" void kernel_launch(void* const* d_in, const int* in_sizes, int n_in,
                              void* d_out, int out_size)
{
    const float* pos   = (const float*)d_in[0];
    const float* rx    = (const float*)d_in[1];
    const float* table = (const float*)d_in[2];
    const float* W1    = (const float*)d_in[3];
    const float* W2    = (const float*)d_in[4];
    const float* aabb  = (const float*)d_in[5];
    const int*   degp  = (n_in > 6) ? (const int*)d_in[6] : nullptr;

    int N = in_sizes[0] / 3;

    for (int base = 0; base < N; base += CH) {
        int chunk = (N - base < CH) ? (N - base) : CH;
        dim3 gridA((chunk + BLOCKA - 1) / BLOCKA, NLEV);
        ngp_encode_kernel<<<gridA, BLOCKA>>>(pos, table, aabb, base, chunk);
        int gridB = (chunk + BLOCKB - 1) / BLOCKB;
        ngp_mlp_kernel<<<gridB, BLOCKB>>>(pos, rx, W1, W2, aabb, degp,
                                          (float*)d_out, base, chunk, N);
    }
}

// round 9
// speedup vs baseline: 1.3985x; 1.1244x over previous
#include <cuda_runtime.h>
#include <math.h>
#include <stdint.h>

#define TBITS 19
#define TSIZE (1u << TBITS)
#define TMASK (TSIZE - 1u)
#define NLEV 16
#define BLOCKA 256
#define BLOCKB 128
#define CH 131072  // 2 chunks; double-buffered scratch; B grid=1024 blocks
#define MAXCHUNKS 8

// double-buffered scratch: per (level l, slot k) a float2 plane of CH points
//   k=0: (F[2l], F[2l+1]) ; k=1: (Gx0,Gx1) ; k=2: (Gy0,Gy1) ; k=3: (Gz0,Gz1)
__device__ float2 g_scratch[2][64 * CH];

__device__ __forceinline__ float shY(int c, float x, float y, float z,
                                     float xx, float yy, float zz,
                                     float xy, float yz, float xz)
{
    switch (c) {
    case 0:  return 0.28209479177387814f;
    case 1:  return -0.4886025119029199f * y;
    case 2:  return  0.4886025119029199f * z;
    case 3:  return -0.4886025119029199f * x;
    case 4:  return  1.0925484305920792f * xy;
    case 5:  return -1.0925484305920792f * yz;
    case 6:  return  0.31539156525252005f * (2.f * zz - xx - yy);
    case 7:  return -1.0925484305920792f * xz;
    case 8:  return  0.5462742152960396f * (xx - yy);
    case 9:  return -0.5900435899266435f * y * (3.f * xx - yy);
    case 10: return  2.890611442640554f  * xy * z;
    case 11: return -0.4570457994644658f * y * (4.f * zz - xx - yy);
    case 12: return  0.3731763325901154f * z * (2.f * zz - 3.f * xx - 3.f * yy);
    case 13: return -0.4570457994644658f * x * (4.f * zz - xx - yy);
    case 14: return  1.445305721320277f  * z * (xx - yy);
    case 15: return -0.5900435899266435f * x * (xx - 3.f * yy);
    }
    return 0.f;
}

// ---------------- Kernel A: hash-grid gather, one (point, level) per thread ----
__global__ __launch_bounds__(BLOCKA)
void ngp_encode_kernel(const float* __restrict__ pos,
                       const float* __restrict__ table,
                       const float* __restrict__ aabb,
                       int baseN, int chunk, int buf)
{
    __shared__ float sres;
    const int l = blockIdx.y;
    if (threadIdx.x == 0) {
        // Replicate reference: s = exp((ln(4096)-ln(16))/15); res_l = f32(16 * s^l)
        double s = exp(0.36967849629863747);
        sres = (float)(16.0 * pow(s, (double)l));
    }
    __syncthreads();

    const int n = blockIdx.x * BLOCKA + threadIdx.x;
    if (n >= chunk) return;
    const int ng = baseN + n;

    float P0 = pos[3 * ng + 0], P1 = pos[3 * ng + 1], P2 = pos[3 * ng + 2];
    float a0 = aabb[0], a1 = aabb[1], a2 = aabb[2];
    float s0 = fmaxf(aabb[3] - a0, 1e-6f);
    float s1 = fmaxf(aabb[4] - a1, 1e-6f);
    float s2 = fmaxf(aabb[5] - a2, 1e-6f);
    float q0 = __fdiv_rn(P0 - a0, s0);
    float q1 = __fdiv_rn(P1 - a1, s1);
    float q2 = __fdiv_rn(P2 - a2, s2);
    float pn0 = fminf(fmaxf(q0, 0.f), 1.f);
    float pn1 = fminf(fmaxf(q1, 0.f), 1.f);
    float pn2 = fminf(fmaxf(q2, 0.f), 1.f);

    const float res = sres;
    float px = pn0 * res, py = pn1 * res, pz = pn2 * res;
    float fx = floorf(px), fy = floorf(py), fz = floorf(pz);
    float wx = px - fx, wy = py - fy, wz = pz - fz;
    unsigned ux = (unsigned)fx, uy = (unsigned)fy, uz = (unsigned)fz;
    unsigned hx0 = ux,                hx1 = ux + 1u;
    unsigned hy0 = uy * 2654435761u,  hy1 = (uy + 1u) * 2654435761u;
    unsigned hz0 = uz * 805459861u,   hz1 = (uz + 1u) * 805459861u;
    const float2* tab = ((const float2*)table) + (size_t)l * TSIZE;

    // batch all 8 gathers first (max MLP), then accumulate in the SAME order
    float2 fv[8];
    #pragma unroll
    for (int c = 0; c < 8; c++) {
        const int bx = (c >> 2) & 1, by = (c >> 1) & 1, bz = c & 1;
        unsigned hh = (bx ? hx1 : hx0) ^ (by ? hy1 : hy0) ^ (bz ? hz1 : hz0);
        fv[c] = __ldg(&tab[hh & TMASK]);
    }

    float f0a = 0.f, f0b = 0.f, f1a = 0.f, f1b = 0.f;
    float gx0a = 0.f, gx0b = 0.f, gx1a = 0.f, gx1b = 0.f;
    float gy0a = 0.f, gy0b = 0.f, gy1a = 0.f, gy1b = 0.f;
    float gz0a = 0.f, gz0b = 0.f, gz1a = 0.f, gz1b = 0.f;

    #pragma unroll
    for (int c = 0; c < 8; c++) {
        const int bx = (c >> 2) & 1, by = (c >> 1) & 1, bz = c & 1;
        float2 f = fv[c];
        float tx = bx ? wx : (1.f - wx);
        float ty = by ? wy : (1.f - wy);
        float tz = bz ? wz : (1.f - wz);
        float pyz = ty * tz;
        float pxz = tx * tz;
        float pxy = tx * ty;
        float wc  = tx * pyz;
        float sx = bx ? pyz : -pyz;
        float sy = by ? pxz : -pxz;
        float sz = bz ? pxy : -pxy;
        if (c & 1) {
            f0b = fmaf(f.x, wc, f0b);   f1b = fmaf(f.y, wc, f1b);
            gx0b = fmaf(f.x, sx, gx0b); gx1b = fmaf(f.y, sx, gx1b);
            gy0b = fmaf(f.x, sy, gy0b); gy1b = fmaf(f.y, sy, gy1b);
            gz0b = fmaf(f.x, sz, gz0b); gz1b = fmaf(f.y, sz, gz1b);
        } else {
            f0a = fmaf(f.x, wc, f0a);   f1a = fmaf(f.y, wc, f1a);
            gx0a = fmaf(f.x, sx, gx0a); gx1a = fmaf(f.y, sx, gx1a);
            gy0a = fmaf(f.x, sy, gy0a); gy1a = fmaf(f.y, sy, gy1a);
            gz0a = fmaf(f.x, sz, gz0a); gz1a = fmaf(f.y, sz, gz1a);
        }
    }

    float2* S = g_scratch[buf];
    S[(size_t)(l * 4 + 0) * CH + n] = make_float2(f0a + f0b, f1a + f1b);
    S[(size_t)(l * 4 + 1) * CH + n] = make_float2((gx0a + gx0b) * res, (gx1a + gx1b) * res);
    S[(size_t)(l * 4 + 2) * CH + n] = make_float2((gy0a + gy0b) * res, (gy1a + gy1b) * res);
    S[(size_t)(l * 4 + 3) * CH + n] = make_float2((gz0a + gz0b) * res, (gz1a + gz1b) * res);
}

// ---------------- Kernel B: MLP fwd + bwd + SH, streaming F/G from scratch ----
__global__ __launch_bounds__(BLOCKB, 5)
void ngp_mlp_kernel(const float* __restrict__ pos,
                    const float* __restrict__ rx,
                    const float* __restrict__ W1,
                    const float* __restrict__ W2,
                    const float* __restrict__ aabb,
                    const int*   __restrict__ degp,
                    float* __restrict__ out,
                    int baseN, int chunk, int N, int buf)
{
    __shared__ float sW1[1024];
    __shared__ float sW2[1024];
    __shared__ __align__(16) float sOut[BLOCKB * 39];

    const int tid = threadIdx.x;
    for (int i = tid; i < 1024; i += BLOCKB) {
        sW1[i] = W1[i];
        sW2[i] = W2[i];
    }
    __syncthreads();

    const int n = blockIdx.x * BLOCKB + tid;
    const int ng = baseN + n;
    const float C0f = 0.28209479177387814f;
    const double C0d = 0.28209479177387814;
    const float2* S = g_scratch[buf];

    if (n < chunk) {
        float P0 = pos[3 * ng + 0], P1 = pos[3 * ng + 1], P2 = pos[3 * ng + 2];
        float a0 = aabb[0], a1 = aabb[1], a2 = aabb[2];
        float s0 = fmaxf(aabb[3] - a0, 1e-6f);
        float s1 = fmaxf(aabb[4] - a1, 1e-6f);
        float s2 = fmaxf(aabb[5] - a2, 1e-6f);
        float q0 = __fdiv_rn(P0 - a0, s0);
        float q1 = __fdiv_rn(P1 - a1, s1);
        float q2 = __fdiv_rn(P2 - a2, s2);
        bool sel = (q0 >= 0.f) && (q0 <= 1.f) &&
                   (q1 >= 0.f) && (q1 <= 1.f) &&
                   (q2 >= 0.f) && (q2 <= 1.f);

        // ---- load F from scratch (coalesced float2) ----
        float F[32];
        #pragma unroll
        for (int l = 0; l < NLEV; l++) {
            float2 fl = __ldg(&S[(size_t)(l * 4 + 0) * CH + n]);
            F[2 * l] = fl.x; F[2 * l + 1] = fl.y;
        }

        // ---- MLP layer 1: h = relu(F @ W1), 4-way split (F dies here) ----
        float h[32];
        #pragma unroll
        for (int j = 0; j < 32; j++) {
            float a0_ = 0.f, a1_ = 0.f, a2_ = 0.f, a3_ = 0.f;
            #pragma unroll
            for (int i = 0; i < 32; i += 4) {
                a0_ = fmaf(F[i],     sW1[(i)     * 32 + j], a0_);
                a1_ = fmaf(F[i + 1], sW1[(i + 1) * 32 + j], a1_);
                a2_ = fmaf(F[i + 2], sW1[(i + 2) * 32 + j], a2_);
                a3_ = fmaf(F[i + 3], sW1[(i + 3) * 32 + j], a3_);
            }
            h[j] = fmaxf((a0_ + a2_) + (a1_ + a3_), 0.f);
        }

        // ---- view direction + SH, layer 2 early (before backward) ----
        int deg = 3;
        if (degp) {
            int v = degp[0];
            if (v >= 0 && v <= 8) deg = v;
        }
        int nact = (deg + 1) * (deg + 1);
        float dx = rx[0] - P0, dy = rx[1] - P1, dz = rx[2] - P2;
        float dn = __fsqrt_rn(dx * dx + dy * dy + dz * dz);
        float dnc = fmaxf(dn, 1e-20f);
        float X = __fdiv_rn(dx, dnc), Y = __fdiv_rn(dy, dnc), Z = __fdiv_rn(dz, dnc);
        float xx = X * X, yy = Y * Y, zz = Z * Z;
        float xy = X * Y, yz = Y * Z, xz = X * Z;

        float* row = &sOut[tid * 39];
        float scat0 = 0.f, scat1 = 0.f;
        #pragma unroll
        for (int c = 0; c < 16; c++) {
            float v0a = 0.f, v0b = 0.f, v1a = 0.f, v1b = 0.f;
            #pragma unroll
            for (int j = 0; j < 32; j += 2) {
                v0a = fmaf(h[j],     sW2[(j)     * 32 + 2 * c],     v0a);
                v1a = fmaf(h[j],     sW2[(j)     * 32 + 2 * c + 1], v1a);
                v0b = fmaf(h[j + 1], sW2[(j + 1) * 32 + 2 * c],     v0b);
                v1b = fmaf(h[j + 1], sW2[(j + 1) * 32 + 2 * c + 1], v1b);
            }
            float v0 = v0a + v0b, v1 = v1a + v1b;
            float Yc = shY(c, X, Y, Z, xx, yy, zz, xy, yz, xz);
            if (c < nact) {
                scat0 = fmaf(Yc, v0, scat0);
                scat1 = fmaf(Yc, v1, scat1);
            }
            row[7 + 2 * c]     = sel ? v0 : 0.f;
            row[7 + 2 * c + 1] = sel ? v1 : 0.f;
        }
        row[2] = sel ? scat0 : 0.f;
        row[3] = sel ? scat1 : 0.f;

        // ---- dens: fp64 accumulation (cancellation-prone), f32 everything else ----
        double dd0 = 0.0, dd1 = 0.0;
        #pragma unroll
        for (int j = 0; j < 32; j++) {
            double hj = (double)h[j];
            dd0 = fma(hj, (double)sW2[j * 32 + 0], dd0);
            dd1 = fma(hj, (double)sW2[j * 32 + 1], dd1);
        }
        dd0 *= C0d; dd1 *= C0d;
        float dens0 = (float)dd0, dens1 = (float)dd1;
        row[0] = sel ? dens0 : 0.f;
        row[1] = sel ? dens1 : 0.f;

        // ---- backward: f32 div/sqrt (exact ops, no amplification) ----
        float rr2 = (float)(dd0 * dd0 + dd1 * dd1);
        float rf = __fsqrt_rn(rr2);
        float uf0 = 0.f, uf1 = 0.f;
        if (rf > 0.f) { uf0 = __fdiv_rn(dens0, rf); uf1 = __fdiv_rn(dens1, rf); }
        float cu0 = C0f * uf0, cu1 = C0f * uf1;

        float gj[32];
        #pragma unroll
        for (int j = 0; j < 32; j++) {
            float v = fmaf(cu0, sW2[j * 32 + 0], cu1 * sW2[j * 32 + 1]);
            gj[j] = (h[j] > 0.f) ? v : 0.f;
        }

        float df[32];
        #pragma unroll
        for (int i = 0; i < 32; i++) {
            float a0_ = 0.f, a1_ = 0.f, a2_ = 0.f, a3_ = 0.f;
            #pragma unroll
            for (int j = 0; j < 32; j += 4) {
                a0_ = fmaf(gj[j],     sW1[i * 32 + j],     a0_);
                a1_ = fmaf(gj[j + 1], sW1[i * 32 + j + 1], a1_);
                a2_ = fmaf(gj[j + 2], sW1[i * 32 + j + 2], a2_);
                a3_ = fmaf(gj[j + 3], sW1[i * 32 + j + 3], a3_);
            }
            df[i] = (a0_ + a2_) + (a1_ + a3_);
        }

        // ---- final gradient reduction: fp64 accumulation, f32 normalize ----
        double gpx = 0.0, gpy = 0.0, gpz = 0.0;
        #pragma unroll
        for (int l = 0; l < NLEV; l++) {
            double d0 = (double)df[2 * l], d1 = (double)df[2 * l + 1];
            float2 gx = __ldg(&S[(size_t)(l * 4 + 1) * CH + n]);
            float2 gy = __ldg(&S[(size_t)(l * 4 + 2) * CH + n]);
            float2 gz = __ldg(&S[(size_t)(l * 4 + 3) * CH + n]);
            gpx = fma(d0, (double)gx.x, fma(d1, (double)gx.y, gpx));
            gpy = fma(d0, (double)gy.x, fma(d1, (double)gy.y, gpy));
            gpz = fma(d0, (double)gz.x, fma(d1, (double)gz.y, gpz));
        }
        float gw0 = __fdiv_rn((float)gpx, s0);
        float gw1 = __fdiv_rn((float)gpy, s1);
        float gw2 = __fdiv_rn((float)gpz, s2);
        float gn = __fsqrt_rn(gw0 * gw0 + gw1 * gw1 + gw2 * gw2);
        float gd = fmaxf(gn, 1e-20f);
        row[4] = sel ? __fdiv_rn(-gw0, gd) : 0.f;
        row[5] = sel ? __fdiv_rn(-gw1, gd) : 0.f;
        row[6] = sel ? __fdiv_rn(-gw2, gd) : 0.f;
    }

    __syncthreads();

    // ---- coalesced staged output ----
    int base = baseN + blockIdx.x * BLOCKB;
    int npts = N - base;
    if (npts >= BLOCKB) {
        const float4* s4 = (const float4*)sOut;
        float4* o4 = (float4*)(out + (size_t)base * 39);
        #pragma unroll 4
        for (int i = tid; i < (BLOCKB * 39) / 4; i += BLOCKB)
            o4[i] = s4[i];
    } else if (npts > 0) {
        for (int i = tid; i < npts * 39; i += BLOCKB)
            out[(size_t)base * 39 + i] = sOut[i];
    }
}

extern "C" void kernel_launch(void* const* d_in, const int* in_sizes, int n_in,
                              void* d_out, int out_size)
{
    const float* pos   = (const float*)d_in[0];
    const float* rx    = (const float*)d_in[1];
    const float* table = (const float*)d_in[2];
    const float* W1    = (const float*)d_in[3];
    const float* W2    = (const float*)d_in[4];
    const float* aabb  = (const float*)d_in[5];
    const int*   degp  = (n_in > 6) ? (const int*)d_in[6] : nullptr;

    int N = in_sizes[0] / 3;

    // one-time stream/event creation (host-side only; happens on the first,
    // non-captured correctness call)
    static cudaStream_t strA = nullptr, strB = nullptr;
    static cudaEvent_t evRoot = nullptr, evA[MAXCHUNKS], evDone = nullptr;
    if (!strA) {
        cudaStreamCreateWithFlags(&strA, cudaStreamNonBlocking);
        cudaStreamCreateWithFlags(&strB, cudaStreamNonBlocking);
        cudaEventCreateWithFlags(&evRoot, cudaEventDisableTiming);
        cudaEventCreateWithFlags(&evDone, cudaEventDisableTiming);
        for (int i = 0; i < MAXCHUNKS; i++)
            cudaEventCreateWithFlags(&evA[i], cudaEventDisableTiming);
    }

    // fork both worker streams from the caller's (default) stream
    cudaEventRecord(evRoot, 0);
    cudaStreamWaitEvent(strA, evRoot, 0);
    cudaStreamWaitEvent(strB, evRoot, 0);

    int nchunks = (N + CH - 1) / CH;
    if (nchunks > MAXCHUNKS) nchunks = MAXCHUNKS;  // N<=MAXCHUNKS*CH by problem size

    for (int i = 0; i < nchunks; i++) {
        int base = i * CH;
        int chunk = (N - base < CH) ? (N - base) : CH;
        int buf = i & 1;
        dim3 gridA((chunk + BLOCKA - 1) / BLOCKA, NLEV);
        ngp_encode_kernel<<<gridA, BLOCKA, 0, strA>>>(pos, table, aabb,
                                                      base, chunk, buf);
        cudaEventRecord(evA[i], strA);
        cudaStreamWaitEvent(strB, evA[i], 0);
        int gridB = (chunk + BLOCKB - 1) / BLOCKB;
        ngp_mlp_kernel<<<gridB, BLOCKB, 0, strB>>>(pos, rx, W1, W2, aabb, degp,
                                                   (float*)d_out, base, chunk,
                                                   N, buf);
    }

    // rejoin into the caller's stream
    cudaEventRecord(evDone, strB);
    cudaStreamWaitEvent(0, evDone, 0);
}

// round 10
// speedup vs baseline: 2.5434x; 1.8186x over previous
#include <cuda_runtime.h>
#include <math.h>
#include <stdint.h>

#define TBITS 19
#define TSIZE (1u << TBITS)
#define TMASK (TSIZE - 1u)
#define NLEV 16
#define BLOCKA 256
#define BLOCKB 128
#define CH 131072  // 2 chunks; double-buffered scratch; B grid=1024 blocks
#define MAXCHUNKS 8

// double-buffered scratch: per (level l, slot k) a float2 plane of CH points
//   k=0: (F[2l], F[2l+1]) ; k=1: (Gx0,Gx1) ; k=2: (Gy0,Gy1) ; k=3: (Gz0,Gz1)
__device__ float2 g_scratch[2][64 * CH];

// weights in constant memory: FFMA takes c[bank][ofs] operand directly (no LDS)
__constant__ float cW1[1024];
__constant__ float cW2[1024];

__device__ __forceinline__ float shY(int c, float x, float y, float z,
                                     float xx, float yy, float zz,
                                     float xy, float yz, float xz)
{
    switch (c) {
    case 0:  return 0.28209479177387814f;
    case 1:  return -0.4886025119029199f * y;
    case 2:  return  0.4886025119029199f * z;
    case 3:  return -0.4886025119029199f * x;
    case 4:  return  1.0925484305920792f * xy;
    case 5:  return -1.0925484305920792f * yz;
    case 6:  return  0.31539156525252005f * (2.f * zz - xx - yy);
    case 7:  return -1.0925484305920792f * xz;
    case 8:  return  0.5462742152960396f * (xx - yy);
    case 9:  return -0.5900435899266435f * y * (3.f * xx - yy);
    case 10: return  2.890611442640554f  * xy * z;
    case 11: return -0.4570457994644658f * y * (4.f * zz - xx - yy);
    case 12: return  0.3731763325901154f * z * (2.f * zz - 3.f * xx - 3.f * yy);
    case 13: return -0.4570457994644658f * x * (4.f * zz - xx - yy);
    case 14: return  1.445305721320277f  * z * (xx - yy);
    case 15: return -0.5900435899266435f * x * (xx - 3.f * yy);
    }
    return 0.f;
}

// ---------------- Kernel A: hash-grid gather, one (point, level) per thread ----
__global__ __launch_bounds__(BLOCKA)
void ngp_encode_kernel(const float* __restrict__ pos,
                       const float* __restrict__ table,
                       const float* __restrict__ aabb,
                       int baseN, int chunk, int buf)
{
    __shared__ float sres;
    const int l = blockIdx.y;
    if (threadIdx.x == 0) {
        // Replicate reference: s = exp((ln(4096)-ln(16))/15); res_l = f32(16 * s^l)
        double s = exp(0.36967849629863747);
        sres = (float)(16.0 * pow(s, (double)l));
    }
    __syncthreads();

    const int n = blockIdx.x * BLOCKA + threadIdx.x;
    if (n >= chunk) return;
    const int ng = baseN + n;

    float P0 = pos[3 * ng + 0], P1 = pos[3 * ng + 1], P2 = pos[3 * ng + 2];
    float a0 = aabb[0], a1 = aabb[1], a2 = aabb[2];
    float s0 = fmaxf(aabb[3] - a0, 1e-6f);
    float s1 = fmaxf(aabb[4] - a1, 1e-6f);
    float s2 = fmaxf(aabb[5] - a2, 1e-6f);
    float q0 = __fdiv_rn(P0 - a0, s0);
    float q1 = __fdiv_rn(P1 - a1, s1);
    float q2 = __fdiv_rn(P2 - a2, s2);
    float pn0 = fminf(fmaxf(q0, 0.f), 1.f);
    float pn1 = fminf(fmaxf(q1, 0.f), 1.f);
    float pn2 = fminf(fmaxf(q2, 0.f), 1.f);

    const float res = sres;
    float px = pn0 * res, py = pn1 * res, pz = pn2 * res;
    float fx = floorf(px), fy = floorf(py), fz = floorf(pz);
    float wx = px - fx, wy = py - fy, wz = pz - fz;
    unsigned ux = (unsigned)fx, uy = (unsigned)fy, uz = (unsigned)fz;
    unsigned hx0 = ux,                hx1 = ux + 1u;
    unsigned hy0 = uy * 2654435761u,  hy1 = (uy + 1u) * 2654435761u;
    unsigned hz0 = uz * 805459861u,   hz1 = (uz + 1u) * 805459861u;
    const float2* tab = ((const float2*)table) + (size_t)l * TSIZE;

    // batch all 8 gathers first (max MLP), then accumulate in the SAME order
    float2 fv[8];
    #pragma unroll
    for (int c = 0; c < 8; c++) {
        const int bx = (c >> 2) & 1, by = (c >> 1) & 1, bz = c & 1;
        unsigned hh = (bx ? hx1 : hx0) ^ (by ? hy1 : hy0) ^ (bz ? hz1 : hz0);
        fv[c] = __ldg(&tab[hh & TMASK]);
    }

    float f0a = 0.f, f0b = 0.f, f1a = 0.f, f1b = 0.f;
    float gx0a = 0.f, gx0b = 0.f, gx1a = 0.f, gx1b = 0.f;
    float gy0a = 0.f, gy0b = 0.f, gy1a = 0.f, gy1b = 0.f;
    float gz0a = 0.f, gz0b = 0.f, gz1a = 0.f, gz1b = 0.f;

    #pragma unroll
    for (int c = 0; c < 8; c++) {
        const int bx = (c >> 2) & 1, by = (c >> 1) & 1, bz = c & 1;
        float2 f = fv[c];
        float tx = bx ? wx : (1.f - wx);
        float ty = by ? wy : (1.f - wy);
        float tz = bz ? wz : (1.f - wz);
        float pyz = ty * tz;
        float pxz = tx * tz;
        float pxy = tx * ty;
        float wc  = tx * pyz;
        float sx = bx ? pyz : -pyz;
        float sy = by ? pxz : -pxz;
        float sz = bz ? pxy : -pxy;
        if (c & 1) {
            f0b = fmaf(f.x, wc, f0b);   f1b = fmaf(f.y, wc, f1b);
            gx0b = fmaf(f.x, sx, gx0b); gx1b = fmaf(f.y, sx, gx1b);
            gy0b = fmaf(f.x, sy, gy0b); gy1b = fmaf(f.y, sy, gy1b);
            gz0b = fmaf(f.x, sz, gz0b); gz1b = fmaf(f.y, sz, gz1b);
        } else {
            f0a = fmaf(f.x, wc, f0a);   f1a = fmaf(f.y, wc, f1a);
            gx0a = fmaf(f.x, sx, gx0a); gx1a = fmaf(f.y, sx, gx1a);
            gy0a = fmaf(f.x, sy, gy0a); gy1a = fmaf(f.y, sy, gy1a);
            gz0a = fmaf(f.x, sz, gz0a); gz1a = fmaf(f.y, sz, gz1a);
        }
    }

    float2* S = g_scratch[buf];
    S[(size_t)(l * 4 + 0) * CH + n] = make_float2(f0a + f0b, f1a + f1b);
    S[(size_t)(l * 4 + 1) * CH + n] = make_float2((gx0a + gx0b) * res, (gx1a + gx1b) * res);
    S[(size_t)(l * 4 + 2) * CH + n] = make_float2((gy0a + gy0b) * res, (gy1a + gy1b) * res);
    S[(size_t)(l * 4 + 3) * CH + n] = make_float2((gz0a + gz0b) * res, (gz1a + gz1b) * res);
}

// ---------------- Kernel B: MLP fwd + bwd + SH, const-mem weights ----
__global__ __launch_bounds__(BLOCKB, 5)
void ngp_mlp_kernel(const float* __restrict__ pos,
                    const float* __restrict__ rx,
                    const float* __restrict__ aabb,
                    const int*   __restrict__ degp,
                    float* __restrict__ out,
                    int baseN, int chunk, int N, int buf)
{
    __shared__ __align__(16) float sOut[BLOCKB * 39];

    const int tid = threadIdx.x;
    const int n = blockIdx.x * BLOCKB + tid;
    const int ng = baseN + n;
    const float C0f = 0.28209479177387814f;
    const double C0d = 0.28209479177387814;
    const float2* S = g_scratch[buf];

    if (n < chunk) {
        float P0 = pos[3 * ng + 0], P1 = pos[3 * ng + 1], P2 = pos[3 * ng + 2];
        float a0 = aabb[0], a1 = aabb[1], a2 = aabb[2];
        float s0 = fmaxf(aabb[3] - a0, 1e-6f);
        float s1 = fmaxf(aabb[4] - a1, 1e-6f);
        float s2 = fmaxf(aabb[5] - a2, 1e-6f);
        float q0 = __fdiv_rn(P0 - a0, s0);
        float q1 = __fdiv_rn(P1 - a1, s1);
        float q2 = __fdiv_rn(P2 - a2, s2);
        bool sel = (q0 >= 0.f) && (q0 <= 1.f) &&
                   (q1 >= 0.f) && (q1 <= 1.f) &&
                   (q2 >= 0.f) && (q2 <= 1.f);

        // ---- load F from scratch (coalesced float2) ----
        float F[32];
        #pragma unroll
        for (int l = 0; l < NLEV; l++) {
            float2 fl = __ldg(&S[(size_t)(l * 4 + 0) * CH + n]);
            F[2 * l] = fl.x; F[2 * l + 1] = fl.y;
        }

        // ---- MLP layer 1: h = relu(F @ W1), const-operand FFMA ----
        float h[32];
        #pragma unroll
        for (int j = 0; j < 32; j++) {
            float a0_ = 0.f, a1_ = 0.f, a2_ = 0.f, a3_ = 0.f;
            #pragma unroll
            for (int i = 0; i < 32; i += 4) {
                a0_ = fmaf(F[i],     cW1[(i)     * 32 + j], a0_);
                a1_ = fmaf(F[i + 1], cW1[(i + 1) * 32 + j], a1_);
                a2_ = fmaf(F[i + 2], cW1[(i + 2) * 32 + j], a2_);
                a3_ = fmaf(F[i + 3], cW1[(i + 3) * 32 + j], a3_);
            }
            h[j] = fmaxf((a0_ + a2_) + (a1_ + a3_), 0.f);
        }

        // ---- view direction + SH, layer 2 early (before backward) ----
        int deg = 3;
        if (degp) {
            int v = degp[0];
            if (v >= 0 && v <= 8) deg = v;
        }
        int nact = (deg + 1) * (deg + 1);
        float dx = rx[0] - P0, dy = rx[1] - P1, dz = rx[2] - P2;
        float dn = __fsqrt_rn(dx * dx + dy * dy + dz * dz);
        float dnc = fmaxf(dn, 1e-20f);
        float X = __fdiv_rn(dx, dnc), Y = __fdiv_rn(dy, dnc), Z = __fdiv_rn(dz, dnc);
        float xx = X * X, yy = Y * Y, zz = Z * Z;
        float xy = X * Y, yz = Y * Z, xz = X * Z;

        float* row = &sOut[tid * 39];
        float scat0 = 0.f, scat1 = 0.f;
        #pragma unroll
        for (int c = 0; c < 16; c++) {
            float v0a = 0.f, v0b = 0.f, v1a = 0.f, v1b = 0.f;
            #pragma unroll
            for (int j = 0; j < 32; j += 2) {
                v0a = fmaf(h[j],     cW2[(j)     * 32 + 2 * c],     v0a);
                v1a = fmaf(h[j],     cW2[(j)     * 32 + 2 * c + 1], v1a);
                v0b = fmaf(h[j + 1], cW2[(j + 1) * 32 + 2 * c],     v0b);
                v1b = fmaf(h[j + 1], cW2[(j + 1) * 32 + 2 * c + 1], v1b);
            }
            float v0 = v0a + v0b, v1 = v1a + v1b;
            float Yc = shY(c, X, Y, Z, xx, yy, zz, xy, yz, xz);
            if (c < nact) {
                scat0 = fmaf(Yc, v0, scat0);
                scat1 = fmaf(Yc, v1, scat1);
            }
            row[7 + 2 * c]     = sel ? v0 : 0.f;
            row[7 + 2 * c + 1] = sel ? v1 : 0.f;
        }
        row[2] = sel ? scat0 : 0.f;
        row[3] = sel ? scat1 : 0.f;

        // ---- dens: fp64 accumulation (cancellation-prone) ----
        double dd0 = 0.0, dd1 = 0.0;
        #pragma unroll
        for (int j = 0; j < 32; j++) {
            double hj = (double)h[j];
            dd0 = fma(hj, (double)cW2[j * 32 + 0], dd0);
            dd1 = fma(hj, (double)cW2[j * 32 + 1], dd1);
        }
        dd0 *= C0d; dd1 *= C0d;
        float dens0 = (float)dd0, dens1 = (float)dd1;
        row[0] = sel ? dens0 : 0.f;
        row[1] = sel ? dens1 : 0.f;

        // ---- backward: f32 div/sqrt (exact ops, no amplification) ----
        float rr2 = (float)(dd0 * dd0 + dd1 * dd1);
        float rf = __fsqrt_rn(rr2);
        float uf0 = 0.f, uf1 = 0.f;
        if (rf > 0.f) { uf0 = __fdiv_rn(dens0, rf); uf1 = __fdiv_rn(dens1, rf); }
        float cu0 = C0f * uf0, cu1 = C0f * uf1;

        float gj[32];
        #pragma unroll
        for (int j = 0; j < 32; j++) {
            float v = fmaf(cu0, cW2[j * 32 + 0], cu1 * cW2[j * 32 + 1]);
            gj[j] = (h[j] > 0.f) ? v : 0.f;
        }

        float df[32];
        #pragma unroll
        for (int i = 0; i < 32; i++) {
            float a0_ = 0.f, a1_ = 0.f, a2_ = 0.f, a3_ = 0.f;
            #pragma unroll
            for (int j = 0; j < 32; j += 4) {
                a0_ = fmaf(gj[j],     cW1[i * 32 + j],     a0_);
                a1_ = fmaf(gj[j + 1], cW1[i * 32 + j + 1], a1_);
                a2_ = fmaf(gj[j + 2], cW1[i * 32 + j + 2], a2_);
                a3_ = fmaf(gj[j + 3], cW1[i * 32 + j + 3], a3_);
            }
            df[i] = (a0_ + a2_) + (a1_ + a3_);
        }

        // ---- final gradient reduction: fp64 accumulation, f32 normalize ----
        double gpx = 0.0, gpy = 0.0, gpz = 0.0;
        #pragma unroll
        for (int l = 0; l < NLEV; l++) {
            double d0 = (double)df[2 * l], d1 = (double)df[2 * l + 1];
            float2 gx = __ldg(&S[(size_t)(l * 4 + 1) * CH + n]);
            float2 gy = __ldg(&S[(size_t)(l * 4 + 2) * CH + n]);
            float2 gz = __ldg(&S[(size_t)(l * 4 + 3) * CH + n]);
            gpx = fma(d0, (double)gx.x, fma(d1, (double)gx.y, gpx));
            gpy = fma(d0, (double)gy.x, fma(d1, (double)gy.y, gpy));
            gpz = fma(d0, (double)gz.x, fma(d1, (double)gz.y, gpz));
        }
        float gw0 = __fdiv_rn((float)gpx, s0);
        float gw1 = __fdiv_rn((float)gpy, s1);
        float gw2 = __fdiv_rn((float)gpz, s2);
        float gn = __fsqrt_rn(gw0 * gw0 + gw1 * gw1 + gw2 * gw2);
        float gd = fmaxf(gn, 1e-20f);
        row[4] = sel ? __fdiv_rn(-gw0, gd) : 0.f;
        row[5] = sel ? __fdiv_rn(-gw1, gd) : 0.f;
        row[6] = sel ? __fdiv_rn(-gw2, gd) : 0.f;
    }

    __syncthreads();

    // ---- coalesced staged output ----
    int base = baseN + blockIdx.x * BLOCKB;
    int npts = N - base;
    if (npts >= BLOCKB) {
        const float4* s4 = (const float4*)sOut;
        float4* o4 = (float4*)(out + (size_t)base * 39);
        #pragma unroll 4
        for (int i = tid; i < (BLOCKB * 39) / 4; i += BLOCKB)
            o4[i] = s4[i];
    } else if (npts > 0) {
        for (int i = tid; i < npts * 39; i += BLOCKB)
            out[(size_t)base * 39 + i] = sOut[i];
    }
}

extern "C" void kernel_launch(void* const* d_in, const int* in_sizes, int n_in,
                              void* d_out, int out_size)
{
    const float* pos   = (const float*)d_in[0];
    const float* rx    = (const float*)d_in[1];
    const float* table = (const float*)d_in[2];
    const float* W1    = (const float*)d_in[3];
    const float* W2    = (const float*)d_in[4];
    const float* aabb  = (const float*)d_in[5];
    const int*   degp  = (n_in > 6) ? (const int*)d_in[6] : nullptr;

    int N = in_sizes[0] / 3;

    // one-time stream/event creation (host-side only; happens on the first,
    // non-captured correctness call)
    static cudaStream_t strA = nullptr, strB = nullptr;
    static cudaEvent_t evRoot = nullptr, evA[MAXCHUNKS], evW = nullptr,
                       evDone = nullptr;
    if (!strA) {
        cudaStreamCreateWithFlags(&strA, cudaStreamNonBlocking);
        cudaStreamCreateWithFlags(&strB, cudaStreamNonBlocking);
        cudaEventCreateWithFlags(&evRoot, cudaEventDisableTiming);
        cudaEventCreateWithFlags(&evW, cudaEventDisableTiming);
        cudaEventCreateWithFlags(&evDone, cudaEventDisableTiming);
        for (int i = 0; i < MAXCHUNKS; i++)
            cudaEventCreateWithFlags(&evA[i], cudaEventDisableTiming);
    }

    // fork both worker streams from the caller's (default) stream
    cudaEventRecord(evRoot, 0);
    cudaStreamWaitEvent(strA, evRoot, 0);
    cudaStreamWaitEvent(strB, evRoot, 0);

    // upload weights to constant memory on stream B (B is the only consumer)
    cudaMemcpyToSymbolAsync(cW1, W1, 1024 * sizeof(float), 0,
                            cudaMemcpyDeviceToDevice, strB);
    cudaMemcpyToSymbolAsync(cW2, W2, 1024 * sizeof(float), 0,
                            cudaMemcpyDeviceToDevice, strB);

    int nchunks = (N + CH - 1) / CH;
    if (nchunks > MAXCHUNKS) nchunks = MAXCHUNKS;

    for (int i = 0; i < nchunks; i++) {
        int base = i * CH;
        int chunk = (N - base < CH) ? (N - base) : CH;
        int buf = i & 1;
        dim3 gridA((chunk + BLOCKA - 1) / BLOCKA, NLEV);
        ngp_encode_kernel<<<gridA, BLOCKA, 0, strA>>>(pos, table, aabb,
                                                      base, chunk, buf);
        cudaEventRecord(evA[i], strA);
        cudaStreamWaitEvent(strB, evA[i], 0);
        int gridB = (chunk + BLOCKB - 1) / BLOCKB;
        ngp_mlp_kernel<<<gridB, BLOCKB, 0, strB>>>(pos, rx, aabb, degp,
                                                   (float*)d_out, base, chunk,
                                                   N, buf);
    }

    // rejoin into the caller's stream
    cudaEventRecord(evDone, strB);
    cudaStreamWaitEvent(0, evDone, 0);
}

// round 11
// speedup vs baseline: 2.8430x; 1.1178x over previous
#include <cuda_runtime.h>
#include <math.h>
#include <stdint.h>

#define TBITS 19
#define TSIZE (1u << TBITS)
#define TMASK (TSIZE - 1u)
#define NLEV 16
#define BLOCKA 256
#define BLOCKB 128
#define CH 131072  // 2 chunks; double-buffered scratch; B grid=1024 blocks
#define MAXCHUNKS 8

// double-buffered scratch: per (level l, slot k) a float2 plane of CH points
//   k=0: (F[2l], F[2l+1]) ; k=1: (Gx0,Gx1) ; k=2: (Gy0,Gy1) ; k=3: (Gz0,Gz1)
__device__ float2 g_scratch[2][64 * CH];

// weights in constant memory: FFMA takes c[bank][ofs] operand directly (no LDS)
__constant__ float cW1[1024];
__constant__ float cW2[1024];

// Dot2 building block: s/c = running twoSum accumulator, e = product-error sum.
__device__ __forceinline__ void dot2_term(float a, float b,
                                          float& s, float& c, float& e)
{
    float p = a * b;
    e += fmaf(a, b, -p);         // exact FMA product error
    float t = s + p;             // twoSum(s, p)
    float z = t - s;
    c += (s - (t - z)) + (p - z);
    s = t;
}

__device__ __forceinline__ float shY(int c, float x, float y, float z,
                                     float xx, float yy, float zz,
                                     float xy, float yz, float xz)
{
    switch (c) {
    case 0:  return 0.28209479177387814f;
    case 1:  return -0.4886025119029199f * y;
    case 2:  return  0.4886025119029199f * z;
    case 3:  return -0.4886025119029199f * x;
    case 4:  return  1.0925484305920792f * xy;
    case 5:  return -1.0925484305920792f * yz;
    case 6:  return  0.31539156525252005f * (2.f * zz - xx - yy);
    case 7:  return -1.0925484305920792f * xz;
    case 8:  return  0.5462742152960396f * (xx - yy);
    case 9:  return -0.5900435899266435f * y * (3.f * xx - yy);
    case 10: return  2.890611442640554f  * xy * z;
    case 11: return -0.4570457994644658f * y * (4.f * zz - xx - yy);
    case 12: return  0.3731763325901154f * z * (2.f * zz - 3.f * xx - 3.f * yy);
    case 13: return -0.4570457994644658f * x * (4.f * zz - xx - yy);
    case 14: return  1.445305721320277f  * z * (xx - yy);
    case 15: return -0.5900435899266435f * x * (xx - 3.f * yy);
    }
    return 0.f;
}

// ---------------- Kernel A: hash-grid gather, one (point, level) per thread ----
__global__ __launch_bounds__(BLOCKA)
void ngp_encode_kernel(const float* __restrict__ pos,
                       const float* __restrict__ table,
                       const float* __restrict__ aabb,
                       int baseN, int chunk, int buf)
{
    __shared__ float sres;
    const int l = blockIdx.y;
    if (threadIdx.x == 0) {
        // Replicate reference: s = exp((ln(4096)-ln(16))/15); res_l = f32(16 * s^l)
        double s = exp(0.36967849629863747);
        sres = (float)(16.0 * pow(s, (double)l));
    }
    __syncthreads();

    const int n = blockIdx.x * BLOCKA + threadIdx.x;
    if (n >= chunk) return;
    const int ng = baseN + n;

    float P0 = pos[3 * ng + 0], P1 = pos[3 * ng + 1], P2 = pos[3 * ng + 2];
    float a0 = aabb[0], a1 = aabb[1], a2 = aabb[2];
    float s0 = fmaxf(aabb[3] - a0, 1e-6f);
    float s1 = fmaxf(aabb[4] - a1, 1e-6f);
    float s2 = fmaxf(aabb[5] - a2, 1e-6f);
    float q0 = __fdiv_rn(P0 - a0, s0);
    float q1 = __fdiv_rn(P1 - a1, s1);
    float q2 = __fdiv_rn(P2 - a2, s2);
    float pn0 = fminf(fmaxf(q0, 0.f), 1.f);
    float pn1 = fminf(fmaxf(q1, 0.f), 1.f);
    float pn2 = fminf(fmaxf(q2, 0.f), 1.f);

    const float res = sres;
    float px = pn0 * res, py = pn1 * res, pz = pn2 * res;
    float fx = floorf(px), fy = floorf(py), fz = floorf(pz);
    float wx = px - fx, wy = py - fy, wz = pz - fz;
    unsigned ux = (unsigned)fx, uy = (unsigned)fy, uz = (unsigned)fz;
    unsigned hx0 = ux,                hx1 = ux + 1u;
    unsigned hy0 = uy * 2654435761u,  hy1 = (uy + 1u) * 2654435761u;
    unsigned hz0 = uz * 805459861u,   hz1 = (uz + 1u) * 805459861u;
    const float2* tab = ((const float2*)table) + (size_t)l * TSIZE;

    // batch all 8 gathers first (max MLP), then accumulate in the SAME order
    float2 fv[8];
    #pragma unroll
    for (int c = 0; c < 8; c++) {
        const int bx = (c >> 2) & 1, by = (c >> 1) & 1, bz = c & 1;
        unsigned hh = (bx ? hx1 : hx0) ^ (by ? hy1 : hy0) ^ (bz ? hz1 : hz0);
        fv[c] = __ldg(&tab[hh & TMASK]);
    }

    float f0a = 0.f, f0b = 0.f, f1a = 0.f, f1b = 0.f;
    float gx0a = 0.f, gx0b = 0.f, gx1a = 0.f, gx1b = 0.f;
    float gy0a = 0.f, gy0b = 0.f, gy1a = 0.f, gy1b = 0.f;
    float gz0a = 0.f, gz0b = 0.f, gz1a = 0.f, gz1b = 0.f;

    #pragma unroll
    for (int c = 0; c < 8; c++) {
        const int bx = (c >> 2) & 1, by = (c >> 1) & 1, bz = c & 1;
        float2 f = fv[c];
        float tx = bx ? wx : (1.f - wx);
        float ty = by ? wy : (1.f - wy);
        float tz = bz ? wz : (1.f - wz);
        float pyz = ty * tz;
        float pxz = tx * tz;
        float pxy = tx * ty;
        float wc  = tx * pyz;
        float sx = bx ? pyz : -pyz;
        float sy = by ? pxz : -pxz;
        float sz = bz ? pxy : -pxy;
        if (c & 1) {
            f0b = fmaf(f.x, wc, f0b);   f1b = fmaf(f.y, wc, f1b);
            gx0b = fmaf(f.x, sx, gx0b); gx1b = fmaf(f.y, sx, gx1b);
            gy0b = fmaf(f.x, sy, gy0b); gy1b = fmaf(f.y, sy, gy1b);
            gz0b = fmaf(f.x, sz, gz0b); gz1b = fmaf(f.y, sz, gz1b);
        } else {
            f0a = fmaf(f.x, wc, f0a);   f1a = fmaf(f.y, wc, f1a);
            gx0a = fmaf(f.x, sx, gx0a); gx1a = fmaf(f.y, sx, gx1a);
            gy0a = fmaf(f.x, sy, gy0a); gy1a = fmaf(f.y, sy, gy1a);
            gz0a = fmaf(f.x, sz, gz0a); gz1a = fmaf(f.y, sz, gz1a);
        }
    }

    float2* S = g_scratch[buf];
    S[(size_t)(l * 4 + 0) * CH + n] = make_float2(f0a + f0b, f1a + f1b);
    S[(size_t)(l * 4 + 1) * CH + n] = make_float2((gx0a + gx0b) * res, (gx1a + gx1b) * res);
    S[(size_t)(l * 4 + 2) * CH + n] = make_float2((gy0a + gy0b) * res, (gy1a + gy1b) * res);
    S[(size_t)(l * 4 + 3) * CH + n] = make_float2((gz0a + gz0b) * res, (gz1a + gz1b) * res);
}

// ---------------- Kernel B: MLP fwd + bwd + SH, const-mem weights ----
__global__ __launch_bounds__(BLOCKB, 5)
void ngp_mlp_kernel(const float* __restrict__ pos,
                    const float* __restrict__ rx,
                    const float* __restrict__ aabb,
                    const int*   __restrict__ degp,
                    float* __restrict__ out,
                    int baseN, int chunk, int N, int buf)
{
    __shared__ __align__(16) float sOut[BLOCKB * 39];

    const int tid = threadIdx.x;
    const int n = blockIdx.x * BLOCKB + tid;
    const int ng = baseN + n;
    const float C0f = 0.28209479177387814f;
    const float2* S = g_scratch[buf];

    if (n < chunk) {
        float P0 = pos[3 * ng + 0], P1 = pos[3 * ng + 1], P2 = pos[3 * ng + 2];
        float a0 = aabb[0], a1 = aabb[1], a2 = aabb[2];
        float s0 = fmaxf(aabb[3] - a0, 1e-6f);
        float s1 = fmaxf(aabb[4] - a1, 1e-6f);
        float s2 = fmaxf(aabb[5] - a2, 1e-6f);
        float q0 = __fdiv_rn(P0 - a0, s0);
        float q1 = __fdiv_rn(P1 - a1, s1);
        float q2 = __fdiv_rn(P2 - a2, s2);
        bool sel = (q0 >= 0.f) && (q0 <= 1.f) &&
                   (q1 >= 0.f) && (q1 <= 1.f) &&
                   (q2 >= 0.f) && (q2 <= 1.f);

        // ---- load F from scratch (coalesced float2) ----
        float F[32];
        #pragma unroll
        for (int l = 0; l < NLEV; l++) {
            float2 fl = __ldg(&S[(size_t)(l * 4 + 0) * CH + n]);
            F[2 * l] = fl.x; F[2 * l + 1] = fl.y;
        }

        // ---- MLP layer 1: h = relu(F @ W1), const-operand FFMA ----
        float h[32];
        #pragma unroll
        for (int j = 0; j < 32; j++) {
            float a0_ = 0.f, a1_ = 0.f, a2_ = 0.f, a3_ = 0.f;
            #pragma unroll
            for (int i = 0; i < 32; i += 4) {
                a0_ = fmaf(F[i],     cW1[(i)     * 32 + j], a0_);
                a1_ = fmaf(F[i + 1], cW1[(i + 1) * 32 + j], a1_);
                a2_ = fmaf(F[i + 2], cW1[(i + 2) * 32 + j], a2_);
                a3_ = fmaf(F[i + 3], cW1[(i + 3) * 32 + j], a3_);
            }
            h[j] = fmaxf((a0_ + a2_) + (a1_ + a3_), 0.f);
        }

        // ---- view direction + SH, layer 2 early (before backward) ----
        int deg = 3;
        if (degp) {
            int v = degp[0];
            if (v >= 0 && v <= 8) deg = v;
        }
        int nact = (deg + 1) * (deg + 1);
        float dx = rx[0] - P0, dy = rx[1] - P1, dz = rx[2] - P2;
        float dn = __fsqrt_rn(dx * dx + dy * dy + dz * dz);
        float dnc = fmaxf(dn, 1e-20f);
        float X = __fdiv_rn(dx, dnc), Y = __fdiv_rn(dy, dnc), Z = __fdiv_rn(dz, dnc);
        float xx = X * X, yy = Y * Y, zz = Z * Z;
        float xy = X * Y, yz = Y * Z, xz = X * Z;

        float* row = &sOut[tid * 39];
        float scat0 = 0.f, scat1 = 0.f;
        #pragma unroll
        for (int c = 0; c < 16; c++) {
            float v0a = 0.f, v0b = 0.f, v1a = 0.f, v1b = 0.f;
            #pragma unroll
            for (int j = 0; j < 32; j += 2) {
                v0a = fmaf(h[j],     cW2[(j)     * 32 + 2 * c],     v0a);
                v1a = fmaf(h[j],     cW2[(j)     * 32 + 2 * c + 1], v1a);
                v0b = fmaf(h[j + 1], cW2[(j + 1) * 32 + 2 * c],     v0b);
                v1b = fmaf(h[j + 1], cW2[(j + 1) * 32 + 2 * c + 1], v1b);
            }
            float v0 = v0a + v0b, v1 = v1a + v1b;
            float Yc = shY(c, X, Y, Z, xx, yy, zz, xy, yz, xz);
            if (c < nact) {
                scat0 = fmaf(Yc, v0, scat0);
                scat1 = fmaf(Yc, v1, scat1);
            }
            row[7 + 2 * c]     = sel ? v0 : 0.f;
            row[7 + 2 * c + 1] = sel ? v1 : 0.f;
        }
        row[2] = sel ? scat0 : 0.f;
        row[3] = sel ? scat1 : 0.f;

        // ---- dens: compensated f32 dot (Dot2 ~ fp64 accuracy, FFMA cost) ----
        float sd0 = 0.f, cd0 = 0.f, ed0 = 0.f;
        float sd1 = 0.f, cd1 = 0.f, ed1 = 0.f;
        #pragma unroll
        for (int j = 0; j < 32; j++) {
            dot2_term(h[j], cW2[j * 32 + 0], sd0, cd0, ed0);
            dot2_term(h[j], cW2[j * 32 + 1], sd1, cd1, ed1);
        }
        float dot0 = sd0 + (cd0 + ed0);
        float dot1 = sd1 + (cd1 + ed1);
        float dens0 = C0f * dot0, dens1 = C0f * dot1;
        row[0] = sel ? dens0 : 0.f;
        row[1] = sel ? dens1 : 0.f;

        // ---- backward: f32 div/sqrt (exact ops, no amplification) ----
        float rf = __fsqrt_rn(dens0 * dens0 + dens1 * dens1);
        float uf0 = 0.f, uf1 = 0.f;
        if (rf > 0.f) { uf0 = __fdiv_rn(dens0, rf); uf1 = __fdiv_rn(dens1, rf); }
        float cu0 = C0f * uf0, cu1 = C0f * uf1;

        float gj[32];
        #pragma unroll
        for (int j = 0; j < 32; j++) {
            float v = fmaf(cu0, cW2[j * 32 + 0], cu1 * cW2[j * 32 + 1]);
            gj[j] = (h[j] > 0.f) ? v : 0.f;
        }

        float df[32];
        #pragma unroll
        for (int i = 0; i < 32; i++) {
            float a0_ = 0.f, a1_ = 0.f, a2_ = 0.f, a3_ = 0.f;
            #pragma unroll
            for (int j = 0; j < 32; j += 4) {
                a0_ = fmaf(gj[j],     cW1[i * 32 + j],     a0_);
                a1_ = fmaf(gj[j + 1], cW1[i * 32 + j + 1], a1_);
                a2_ = fmaf(gj[j + 2], cW1[i * 32 + j + 2], a2_);
                a3_ = fmaf(gj[j + 3], cW1[i * 32 + j + 3], a3_);
            }
            df[i] = (a0_ + a2_) + (a1_ + a3_);
        }

        // ---- final gradient reduction: Dot2 f32, then f32 normalize ----
        float sx = 0.f, cx = 0.f, ex = 0.f;
        float sy = 0.f, cy = 0.f, ey = 0.f;
        float sz = 0.f, cz = 0.f, ez = 0.f;
        #pragma unroll
        for (int l = 0; l < NLEV; l++) {
            float d0 = df[2 * l], d1 = df[2 * l + 1];
            float2 gx = __ldg(&S[(size_t)(l * 4 + 1) * CH + n]);
            float2 gy = __ldg(&S[(size_t)(l * 4 + 2) * CH + n]);
            float2 gz = __ldg(&S[(size_t)(l * 4 + 3) * CH + n]);
            dot2_term(d0, gx.x, sx, cx, ex);
            dot2_term(d1, gx.y, sx, cx, ex);
            dot2_term(d0, gy.x, sy, cy, ey);
            dot2_term(d1, gy.y, sy, cy, ey);
            dot2_term(d0, gz.x, sz, cz, ez);
            dot2_term(d1, gz.y, sz, cz, ez);
        }
        float gpx = sx + (cx + ex);
        float gpy = sy + (cy + ey);
        float gpz = sz + (cz + ez);

        float gw0 = __fdiv_rn(gpx, s0);
        float gw1 = __fdiv_rn(gpy, s1);
        float gw2 = __fdiv_rn(gpz, s2);
        float gn = __fsqrt_rn(gw0 * gw0 + gw1 * gw1 + gw2 * gw2);
        float gd = fmaxf(gn, 1e-20f);
        row[4] = sel ? __fdiv_rn(-gw0, gd) : 0.f;
        row[5] = sel ? __fdiv_rn(-gw1, gd) : 0.f;
        row[6] = sel ? __fdiv_rn(-gw2, gd) : 0.f;
    }

    __syncthreads();

    // ---- coalesced staged output ----
    int base = baseN + blockIdx.x * BLOCKB;
    int npts = N - base;
    if (npts >= BLOCKB) {
        const float4* s4 = (const float4*)sOut;
        float4* o4 = (float4*)(out + (size_t)base * 39);
        #pragma unroll 4
        for (int i = tid; i < (BLOCKB * 39) / 4; i += BLOCKB)
            o4[i] = s4[i];
    } else if (npts > 0) {
        for (int i = tid; i < npts * 39; i += BLOCKB)
            out[(size_t)base * 39 + i] = sOut[i];
    }
}

extern "C" void kernel_launch(void* const* d_in, const int* in_sizes, int n_in,
                              void* d_out, int out_size)
{
    const float* pos   = (const float*)d_in[0];
    const float* rx    = (const float*)d_in[1];
    const float* table = (const float*)d_in[2];
    const float* W1    = (const float*)d_in[3];
    const float* W2    = (const float*)d_in[4];
    const float* aabb  = (const float*)d_in[5];
    const int*   degp  = (n_in > 6) ? (const int*)d_in[6] : nullptr;

    int N = in_sizes[0] / 3;

    // one-time stream/event creation (host-side only; happens on the first,
    // non-captured correctness call)
    static cudaStream_t strA = nullptr, strB = nullptr;
    static cudaEvent_t evRoot = nullptr, evA[MAXCHUNKS], evDone = nullptr;
    if (!strA) {
        cudaStreamCreateWithFlags(&strA, cudaStreamNonBlocking);
        cudaStreamCreateWithFlags(&strB, cudaStreamNonBlocking);
        cudaEventCreateWithFlags(&evRoot, cudaEventDisableTiming);
        cudaEventCreateWithFlags(&evDone, cudaEventDisableTiming);
        for (int i = 0; i < MAXCHUNKS; i++)
            cudaEventCreateWithFlags(&evA[i], cudaEventDisableTiming);
    }

    // fork both worker streams from the caller's (default) stream
    cudaEventRecord(evRoot, 0);
    cudaStreamWaitEvent(strA, evRoot, 0);
    cudaStreamWaitEvent(strB, evRoot, 0);

    // upload weights to constant memory on stream B (B is the only consumer)
    cudaMemcpyToSymbolAsync(cW1, W1, 1024 * sizeof(float), 0,
                            cudaMemcpyDeviceToDevice, strB);
    cudaMemcpyToSymbolAsync(cW2, W2, 1024 * sizeof(float), 0,
                            cudaMemcpyDeviceToDevice, strB);

    int nchunks = (N + CH - 1) / CH;
    if (nchunks > MAXCHUNKS) nchunks = MAXCHUNKS;

    for (int i = 0; i < nchunks; i++) {
        int base = i * CH;
        int chunk = (N - base < CH) ? (N - base) : CH;
        int buf = i & 1;
        dim3 gridA((chunk + BLOCKA - 1) / BLOCKA, NLEV);
        ngp_encode_kernel<<<gridA, BLOCKA, 0, strA>>>(pos, table, aabb,
                                                      base, chunk, buf);
        cudaEventRecord(evA[i], strA);
        cudaStreamWaitEvent(strB, evA[i], 0);
        int gridB = (chunk + BLOCKB - 1) / BLOCKB;
        ngp_mlp_kernel<<<gridB, BLOCKB, 0, strB>>>(pos, rx, aabb, degp,
                                                   (float*)d_out, base, chunk,
                                                   N, buf);
    }

    // rejoin into the caller's stream
    cudaEventRecord(evDone, strB);
    cudaStreamWaitEvent(0, evDone, 0);
}